// round 9
// baseline (speedup 1.0000x reference)
#include <cuda_runtime.h>
#include <cuda_fp16.h>
#include <cuda_bf16.h>
#include <cstdint>

// ---------------------------------------------------------------------------
// SimpleGAT on GB300 (sm_103a) — round 9:
//  * CSR build is now: hist_rank (atomicAdd returns per-edge rank, stored
//    sequentially) -> scan (decoupled lookback, one launch) -> scatter_pos
//    (pos = off[dst] + rank[e]; NO atomics). scatter also re-zeroes
//    g_cnt/g_state for the next graph replay (globals are zero-init at load,
//    so call #1 is correct too) — the zero_cnt launch is gone.
//  * K1/K4 on HMMA (mma.sync m16n8k16, fp16 in / fp32 accum); agg output fp16.
//  * CSR branch forked onto stream B, overlapped with K1; join before agg.
//  * global-max softmax stabilization skipped (cancels up to the 1e-9 eps).
// ---------------------------------------------------------------------------

#define N_MAX 100000
#define E_MAX 1600000
#define CHUNK 1024
#define NPART 128

__device__ __half2 g_hh[N_MAX * 32];    // h as half2, row = 32 half2 = 128B
__device__ __half2 g_aggh[N_MAX * 32];  // relu(agg) as half2
__device__ float g_s[N_MAX];
__device__ float g_d[N_MAX];
__device__ int   g_cnt[N_MAX];          // zero at load; re-zeroed by scatter
__device__ int   g_off[N_MAX + 1];
__device__ int   g_rank[E_MAX];
__device__ int   g_srcSorted[E_MAX];
__device__ unsigned long long g_state[NPART];   // zero at load; re-zeroed by scatter

#define FMA2(d, a, b) \
    asm("fma.rn.f32x2 %0, %1, %2, %3;" : "=l"(d) : "l"(a), "l"(b), "l"(d))

__device__ __forceinline__ unsigned long long dup_f32x2(float v)
{
    unsigned long long r;
    asm("mov.b64 %0, {%1, %1};" : "=l"(r) : "r"(__float_as_uint(v)));
    return r;
}

union F2U64 {
    unsigned long long u;
    float2 f;
};

__device__ __forceinline__ uint32_t smem_u32(const void* p)
{
    uint32_t a;
    asm("{ .reg .u64 t; cvta.to.shared.u64 t, %1; cvt.u32.u64 %0, t; }"
        : "=r"(a) : "l"(p));
    return a;
}

// ------------------------- K1: HMMA input GEMM + att proj ------------------
#define K1_STRIDE 272
#define K1_SMA 0
#define K1_SMB (128 * K1_STRIDE)
#define K1_SMEM_TOTAL (128 * K1_STRIDE + 64 * K1_STRIDE)

__global__ __launch_bounds__(256) void gemm_h_hmma(
    const float* __restrict__ x, const float* __restrict__ Wlin,
    const float* __restrict__ att, int N)
{
    extern __shared__ char smem[];
    const uint32_t smem_base = smem_u32(smem);
    const int tid  = threadIdx.x;
    const int wid  = tid >> 5;
    const int lane = tid & 31;
    const int row0 = blockIdx.x * 128;

    {
        const int row  = tid >> 1;
        const int half = tid & 1;
        const int grow = row0 + row;
        char* dst = smem + K1_SMA + row * K1_STRIDE + half * 128;
        if (grow < N) {
            const float4* srcp = (const float4*)&x[(size_t)grow * 128 + half * 64];
#pragma unroll
            for (int j = 0; j < 8; j++) {
                const float4 v0 = srcp[2 * j];
                const float4 v1 = srcp[2 * j + 1];
                __half2 p[4];
                p[0] = __floats2half2_rn(v0.x, v0.y);
                p[1] = __floats2half2_rn(v0.z, v0.w);
                p[2] = __floats2half2_rn(v1.x, v1.y);
                p[3] = __floats2half2_rn(v1.z, v1.w);
                *(uint4*)(dst + j * 16) = *(uint4*)p;
            }
        } else {
            const uint4 z = make_uint4(0u, 0u, 0u, 0u);
#pragma unroll
            for (int j = 0; j < 8; j++)
                *(uint4*)(dst + j * 16) = z;
        }
    }

    {
        const int row = tid >> 2;
        const int q   = tid & 3;
        char* dst = smem + K1_SMB + row * K1_STRIDE + q * 64;
        const float4* srcp = (const float4*)&Wlin[(size_t)row * 128 + q * 32];
#pragma unroll
        for (int j = 0; j < 4; j++) {
            const float4 v0 = srcp[2 * j];
            const float4 v1 = srcp[2 * j + 1];
            __half2 p[4];
            p[0] = __floats2half2_rn(v0.x, v0.y);
            p[1] = __floats2half2_rn(v0.z, v0.w);
            p[2] = __floats2half2_rn(v1.x, v1.y);
            p[3] = __floats2half2_rn(v1.z, v1.w);
            *(uint4*)(dst + j * 16) = *(uint4*)p;
        }
    }
    __syncthreads();

    float acc[8][4];
#pragma unroll
    for (int nt = 0; nt < 8; nt++)
#pragma unroll
        for (int i = 0; i < 4; i++) acc[nt][i] = 0.f;

    const uint32_t aAddrBase = smem_base + K1_SMA +
        (wid * 16 + (lane & 15)) * K1_STRIDE + (lane >> 4) * 16;
    const int grp = lane >> 3;
    const int li  = lane & 7;
    const uint32_t bAddrBase = smem_base + K1_SMB +
        ((grp >> 1) * 8 + li) * K1_STRIDE + (grp & 1) * 16;

#pragma unroll
    for (int ks = 0; ks < 8; ks++) {
        uint32_t a0, a1, a2, a3;
        asm volatile(
            "ldmatrix.sync.aligned.m8n8.x4.shared.b16 {%0,%1,%2,%3}, [%4];"
            : "=r"(a0), "=r"(a1), "=r"(a2), "=r"(a3)
            : "r"(aAddrBase + ks * 32));
#pragma unroll
        for (int nt2 = 0; nt2 < 4; nt2++) {
            uint32_t b0, b1, b2, b3;
            asm volatile(
                "ldmatrix.sync.aligned.m8n8.x4.shared.b16 {%0,%1,%2,%3}, [%4];"
                : "=r"(b0), "=r"(b1), "=r"(b2), "=r"(b3)
                : "r"(bAddrBase + nt2 * 16 * K1_STRIDE + ks * 32));
            float* c0 = acc[nt2 * 2];
            float* c1 = acc[nt2 * 2 + 1];
            asm volatile(
                "mma.sync.aligned.m16n8k16.row.col.f32.f16.f16.f32 "
                "{%0,%1,%2,%3}, {%4,%5,%6,%7}, {%8,%9}, {%0,%1,%2,%3};"
                : "+f"(c0[0]), "+f"(c0[1]), "+f"(c0[2]), "+f"(c0[3])
                : "r"(a0), "r"(a1), "r"(a2), "r"(a3), "r"(b0), "r"(b1));
            asm volatile(
                "mma.sync.aligned.m16n8k16.row.col.f32.f16.f16.f32 "
                "{%0,%1,%2,%3}, {%4,%5,%6,%7}, {%8,%9}, {%0,%1,%2,%3};"
                : "+f"(c1[0]), "+f"(c1[1]), "+f"(c1[2]), "+f"(c1[3])
                : "r"(a0), "r"(a1), "r"(a2), "r"(a3), "r"(b2), "r"(b3));
        }
    }

    float2 aS[8], aD[8];
#pragma unroll
    for (int nt = 0; nt < 8; nt++) {
        const int col = nt * 8 + (lane & 3) * 2;
        aS[nt] = *(const float2*)&att[col];
        aD[nt] = *(const float2*)&att[64 + col];
    }

#pragma unroll
    for (int r = 0; r < 2; r++) {
        const int rowg = row0 + wid * 16 + (lane >> 2) + r * 8;
        const bool ok = (rowg < N);
        float sp = 0.f, dp = 0.f;
#pragma unroll
        for (int nt = 0; nt < 8; nt++) {
            const float c0 = acc[nt][r * 2 + 0];
            const float c1 = acc[nt][r * 2 + 1];
            sp += c0 * aS[nt].x + c1 * aS[nt].y;
            dp += c0 * aD[nt].x + c1 * aD[nt].y;
            if (ok)
                g_hh[(size_t)rowg * 32 + nt * 4 + (lane & 3)] =
                    __floats2half2_rn(c0, c1);
        }
        sp += __shfl_xor_sync(0xffffffffu, sp, 1);
        sp += __shfl_xor_sync(0xffffffffu, sp, 2);
        dp += __shfl_xor_sync(0xffffffffu, dp, 1);
        dp += __shfl_xor_sync(0xffffffffu, dp, 2);
        if ((lane & 3) == 0 && ok) {
            g_s[rowg] = sp;
            g_d[rowg] = dp;
        }
    }
}

// ------------------- H: histogram + per-edge rank (one pass) ---------------
__global__ __launch_bounds__(256) void hist_rank(const int* __restrict__ ei, int E)
{
    const int t = blockIdx.x * blockDim.x + threadIdx.x;
    const int e4 = t * 4;
    if (e4 + 3 < E) {
        const int4 d = *(const int4*)&ei[E + e4];
        int4 r;
        r.x = atomicAdd(&g_cnt[d.x], 1);
        r.y = atomicAdd(&g_cnt[d.y], 1);
        r.z = atomicAdd(&g_cnt[d.z], 1);
        r.w = atomicAdd(&g_cnt[d.w], 1);
        *(int4*)&g_rank[e4] = r;
    } else {
        for (int j = 0; j < 4; j++) {
            const int e = e4 + j;
            if (e < E) g_rank[e] = atomicAdd(&g_cnt[ei[E + e]], 1);
        }
    }
}

// ------------------------- S: one-launch exclusive scan --------------------
__global__ __launch_bounds__(256) void scan_fused(int N, int E, int nb)
{
    const int b = blockIdx.x;
    const int t = threadIdx.x;
    const int idx0 = b * CHUNK + t * 4;

    int v[4];
#pragma unroll
    for (int i = 0; i < 4; i++) {
        const int idx = idx0 + i;
        v[i] = (idx < N) ? g_cnt[idx] : 0;
    }
    const int tsum = v[0] + v[1] + v[2] + v[3];

    __shared__ int sm[256];
    __shared__ int blockBase;
    sm[t] = tsum;
    __syncthreads();
    for (int off = 1; off < 256; off <<= 1) {
        const int add = (t >= off) ? sm[t - off] : 0;
        __syncthreads();
        sm[t] += add;
        __syncthreads();
    }

    if (t == 0) {
        const unsigned long long pkt =
            (1ull << 63) | (unsigned long long)(unsigned)sm[255];
        __threadfence();
        atomicExch(&g_state[b], pkt);
    }

    if (t < 32) {
        int sumPrev = 0;
        for (int base = 0; base < b; base += 32) {
            const int i = base + t;
            if (i < b) {
                unsigned long long pkt;
                do {
                    pkt = atomicAdd(&g_state[i], 0ull);
                } while (!(pkt >> 63));
                sumPrev += (int)(unsigned)(pkt & 0xffffffffull);
            }
        }
#pragma unroll
        for (int m = 16; m >= 1; m >>= 1)
            sumPrev += __shfl_xor_sync(0xffffffffu, sumPrev, m);
        if (t == 0) blockBase = sumPrev;
    }
    __syncthreads();

    int run = sm[t] - tsum + blockBase;
#pragma unroll
    for (int i = 0; i < 4; i++) {
        const int idx = idx0 + i;
        if (idx < N) {
            g_off[idx] = run;
            run += v[i];
        }
    }
    if (b == 0 && t == 0) g_off[N] = E;
}

// ----------------- SC: atomic-free scatter + state re-zero -----------------
__global__ __launch_bounds__(256) void scatter_pos(const int* __restrict__ ei,
                                                   int E, int N)
{
    const int t = blockIdx.x * blockDim.x + threadIdx.x;
    const int e4 = t * 4;
    if (e4 + 3 < E) {
        const int4 s = *(const int4*)&ei[e4];
        const int4 d = *(const int4*)&ei[E + e4];
        const int4 r = *(const int4*)&g_rank[e4];
        g_srcSorted[__ldg(&g_off[d.x]) + r.x] = s.x;
        g_srcSorted[__ldg(&g_off[d.y]) + r.y] = s.y;
        g_srcSorted[__ldg(&g_off[d.z]) + r.z] = s.z;
        g_srcSorted[__ldg(&g_off[d.w]) + r.w] = s.w;
    } else {
        for (int j = 0; j < 4; j++) {
            const int e = e4 + j;
            if (e < E)
                g_srcSorted[__ldg(&g_off[ei[E + e]]) + g_rank[e]] = ei[e];
        }
    }

    // re-zero g_cnt / g_state for the next graph replay (they were consumed
    // by scan above; globals start zeroed at module load, so call #1 is fine)
    if (e4 + 3 < N) {
        *(int4*)&g_cnt[e4] = make_int4(0, 0, 0, 0);
    } else if (e4 < N) {
        for (int j = 0; j < 4; j++)
            if (e4 + j < N) g_cnt[e4 + j] = 0;
    }
    if (t < NPART) g_state[t] = 0ull;
}

// ------------------------- AG: register aggregation ------------------------
__global__ __launch_bounds__(256) void agg_kernel(int N)
{
    const int warp = (blockIdx.x * blockDim.x + threadIdx.x) >> 5;
    if (warp >= N) return;
    const int lane = threadIdx.x & 31;
    const int part = lane & 7;
    const int sub  = lane >> 3;

    const int start = g_off[warp];
    const int end   = g_off[warp + 1];
    const float dnode = g_d[warp];

    unsigned long long acc2[4] = {0ull, 0ull, 0ull, 0ull};
    float wsum = 0.f;

    const int cnt = end - start;
    const int iters = (cnt + 3) >> 2;
    for (int it = 0; it < iters; ++it) {
        const int e = start + it * 4 + sub;
        const bool valid = (e < end);
        const int src = g_srcSorted[valid ? e : 0];
        float ev = g_s[src] + dnode;
        ev = (ev > 0.f) ? ev : 0.2f * ev;
        const float w = valid ? __expf(ev) : 0.f;
        if (part == 0) wsum += w;
        const unsigned long long w2 = dup_f32x2(w);
        const uint4 hvu = *(const uint4*)(((const char*)g_hh) + ((size_t)src * 128 + part * 16));
        const __half2* hp = (const __half2*)&hvu;
#pragma unroll
        for (int j = 0; j < 4; j++) {
            F2U64 hf; hf.f = __half22float2(hp[j]);
            FMA2(acc2[j], hf.u, w2);
        }
    }

#pragma unroll
    for (int j = 0; j < 4; j++) {
        F2U64 a; a.u = acc2[j];
        a.f.x += __shfl_xor_sync(0xffffffffu, a.f.x, 8);
        a.f.y += __shfl_xor_sync(0xffffffffu, a.f.y, 8);
        a.f.x += __shfl_xor_sync(0xffffffffu, a.f.x, 16);
        a.f.y += __shfl_xor_sync(0xffffffffu, a.f.y, 16);
        acc2[j] = a.u;
    }
    wsum += __shfl_xor_sync(0xffffffffu, wsum, 8);
    wsum += __shfl_xor_sync(0xffffffffu, wsum, 16);
    const float den = __shfl_sync(0xffffffffu, wsum, 0) + 1e-9f;

    if (sub == 0) {
        const float inv = 1.f / den;
        __half2 p[4];
#pragma unroll
        for (int j = 0; j < 4; j++) {
            F2U64 a; a.u = acc2[j];
            p[j] = __floats2half2_rn(fmaxf(a.f.x * inv, 0.f),
                                     fmaxf(a.f.y * inv, 0.f));
        }
        *(uint4*)&g_aggh[warp * 32 + part * 4] = *(uint4*)p;
    }
}

// ------------------------- K4: HMMA output GEMM ----------------------------
#define KO_STRIDE 144
#define KO_SMB (128 * KO_STRIDE)

__global__ __launch_bounds__(256) void gemm_out_hmma(
    const float* __restrict__ Wout, const float* __restrict__ bout,
    float* __restrict__ out, int N)
{
    __shared__ char smem[128 * KO_STRIDE + 64 * KO_STRIDE];
    const uint32_t smem_base = smem_u32(smem);
    const int tid  = threadIdx.x;
    const int wid  = tid >> 5;
    const int lane = tid & 31;
    const int row0 = blockIdx.x * 128;

    for (int task = tid; task < 128 * 8; task += 256) {
        const int row = task >> 3;
        const int c   = task & 7;
        const int grow = row0 + row;
        uint4 v = make_uint4(0u, 0u, 0u, 0u);
        if (grow < N) v = *(const uint4*)&g_aggh[(size_t)grow * 32 + c * 4];
        *(uint4*)(smem + row * KO_STRIDE + c * 16) = v;
    }

    {
        const int row = tid >> 2;
        const int q   = tid & 3;
        const float4* srcp = (const float4*)&Wout[(size_t)row * 64 + q * 16];
        char* dst = smem + KO_SMB + row * KO_STRIDE + q * 32;
#pragma unroll
        for (int j = 0; j < 2; j++) {
            const float4 v0 = srcp[2 * j];
            const float4 v1 = srcp[2 * j + 1];
            __half2 p[4];
            p[0] = __floats2half2_rn(v0.x, v0.y);
            p[1] = __floats2half2_rn(v0.z, v0.w);
            p[2] = __floats2half2_rn(v1.x, v1.y);
            p[3] = __floats2half2_rn(v1.z, v1.w);
            *(uint4*)(dst + j * 16) = *(uint4*)p;
        }
    }
    __syncthreads();

    float acc[8][4];
#pragma unroll
    for (int nt = 0; nt < 8; nt++)
#pragma unroll
        for (int i = 0; i < 4; i++) acc[nt][i] = 0.f;

    const uint32_t aAddrBase = smem_base +
        (wid * 16 + (lane & 15)) * KO_STRIDE + (lane >> 4) * 16;
    const int grp = lane >> 3;
    const int li  = lane & 7;
    const uint32_t bAddrBase = smem_base + KO_SMB +
        ((grp >> 1) * 8 + li) * KO_STRIDE + (grp & 1) * 16;

#pragma unroll
    for (int ks = 0; ks < 4; ks++) {
        uint32_t a0, a1, a2, a3;
        asm volatile(
            "ldmatrix.sync.aligned.m8n8.x4.shared.b16 {%0,%1,%2,%3}, [%4];"
            : "=r"(a0), "=r"(a1), "=r"(a2), "=r"(a3)
            : "r"(aAddrBase + ks * 32));
#pragma unroll
        for (int nt2 = 0; nt2 < 4; nt2++) {
            uint32_t b0, b1, b2, b3;
            asm volatile(
                "ldmatrix.sync.aligned.m8n8.x4.shared.b16 {%0,%1,%2,%3}, [%4];"
                : "=r"(b0), "=r"(b1), "=r"(b2), "=r"(b3)
                : "r"(bAddrBase + nt2 * 16 * KO_STRIDE + ks * 32));
            float* c0 = acc[nt2 * 2];
            float* c1 = acc[nt2 * 2 + 1];
            asm volatile(
                "mma.sync.aligned.m16n8k16.row.col.f32.f16.f16.f32 "
                "{%0,%1,%2,%3}, {%4,%5,%6,%7}, {%8,%9}, {%0,%1,%2,%3};"
                : "+f"(c0[0]), "+f"(c0[1]), "+f"(c0[2]), "+f"(c0[3])
                : "r"(a0), "r"(a1), "r"(a2), "r"(a3), "r"(b0), "r"(b1));
            asm volatile(
                "mma.sync.aligned.m16n8k16.row.col.f32.f16.f16.f32 "
                "{%0,%1,%2,%3}, {%4,%5,%6,%7}, {%8,%9}, {%0,%1,%2,%3};"
                : "+f"(c1[0]), "+f"(c1[1]), "+f"(c1[2]), "+f"(c1[3])
                : "r"(a0), "r"(a1), "r"(a2), "r"(a3), "r"(b2), "r"(b3));
        }
    }

    float2 bias[8];
#pragma unroll
    for (int nt = 0; nt < 8; nt++)
        bias[nt] = *(const float2*)&bout[nt * 8 + (lane & 3) * 2];

#pragma unroll
    for (int r = 0; r < 2; r++) {
        const int rowg = row0 + wid * 16 + (lane >> 2) + r * 8;
        if (rowg >= N) continue;
#pragma unroll
        for (int nt = 0; nt < 8; nt++) {
            const int col = nt * 8 + (lane & 3) * 2;
            float2 o;
            o.x = acc[nt][r * 2 + 0] + bias[nt].x;
            o.y = acc[nt][r * 2 + 1] + bias[nt].y;
            *(float2*)&out[(size_t)rowg * 64 + col] = o;
        }
    }
}

// ---------------------------------------------------------------------------
extern "C" void kernel_launch(void* const* d_in, const int* in_sizes, int n_in,
                              void* d_out, int out_size)
{
    const float* x    = (const float*)d_in[0];
    const int*   ei   = (const int*)d_in[1];
    const float* Wlin = (const float*)d_in[2];
    const float* att  = (const float*)d_in[3];
    const float* Wout = (const float*)d_in[4];
    const float* bout = (const float*)d_in[5];
    float* out = (float*)d_out;

    const int N = in_sizes[0] / 128;
    const int E = in_sizes[1] / 2;
    const int nb = (N + CHUNK - 1) / CHUNK;

    static cudaStream_t sB = nullptr;
    static cudaEvent_t evFork = nullptr, evJoin = nullptr;
    static bool attrSet = false;
    if (sB == nullptr) {
        cudaStreamCreateWithFlags(&sB, cudaStreamNonBlocking);
        cudaEventCreateWithFlags(&evFork, cudaEventDisableTiming);
        cudaEventCreateWithFlags(&evJoin, cudaEventDisableTiming);
    }
    if (!attrSet) {
        cudaFuncSetAttribute(gemm_h_hmma,
                             cudaFuncAttributeMaxDynamicSharedMemorySize,
                             K1_SMEM_TOTAL);
        attrSet = true;
    }

    if (sB != nullptr) {
        cudaEventRecord(evFork, 0);
        cudaStreamWaitEvent(sB, evFork, 0);

        hist_rank<<<(E / 4 + 255) / 256 + 1, 256, 0, sB>>>(ei, E);
        scan_fused<<<nb, 256, 0, sB>>>(N, E, nb);
        scatter_pos<<<(E / 4 + 255) / 256 + 1, 256, 0, sB>>>(ei, E, N);
        cudaEventRecord(evJoin, sB);

        gemm_h_hmma<<<(N + 127) / 128, 256, K1_SMEM_TOTAL>>>(x, Wlin, att, N);

        cudaStreamWaitEvent(0, evJoin, 0);
    } else {
        gemm_h_hmma<<<(N + 127) / 128, 256, K1_SMEM_TOTAL>>>(x, Wlin, att, N);
        hist_rank<<<(E / 4 + 255) / 256 + 1, 256>>>(ei, E);
        scan_fused<<<nb, 256>>>(N, E, nb);
        scatter_pos<<<(E / 4 + 255) / 256 + 1, 256>>>(ei, E, N);
    }

    agg_kernel<<<(N * 32 + 255) / 256, 256>>>(N);
    gemm_out_hmma<<<(N + 127) / 128, 256>>>(Wout, bout, out, N);
}

// round 10
// speedup vs baseline: 1.1535x; 1.1535x over previous
#include <cuda_runtime.h>
#include <cuda_fp16.h>
#include <cuda_bf16.h>
#include <cstdint>

// ---------------------------------------------------------------------------
// SimpleGAT on GB300 (sm_103a) — round 10: K1 global loads made warp-linear.
//  R9 profile: gemm_h_hmma 34.7us, L1 71%, HBM 1.49TB/s == 51MB/34.7us ->
//  the scattered per-row load pattern was the bottleneck (32 lines per LDG
//  wavefront). One warp now loads one contiguous 512B row per instruction.
//  * CSR build: hist_rank (atomic returns rank) -> scan (decoupled lookback)
//    -> scatter_pos (atomic-free; re-zeroes g_cnt/g_state for graph replay).
//  * K1/K4 on HMMA (m16n8k16 fp16/fp32); agg output fp16.
//  * CSR branch forked on stream B, overlapped with K1; join before agg.
//  * global-max softmax stabilization skipped (cancels up to the 1e-9 eps).
// ---------------------------------------------------------------------------

#define N_MAX 100000
#define E_MAX 1600000
#define CHUNK 1024
#define NPART 128

__device__ __half2 g_hh[N_MAX * 32];    // h as half2, row = 32 half2 = 128B
__device__ __half2 g_aggh[N_MAX * 32];  // relu(agg) as half2
__device__ float g_s[N_MAX];
__device__ float g_d[N_MAX];
__device__ int   g_cnt[N_MAX];          // zero at load; re-zeroed by scatter
__device__ int   g_off[N_MAX + 1];
__device__ int   g_rank[E_MAX];
__device__ int   g_srcSorted[E_MAX];
__device__ unsigned long long g_state[NPART];   // zero at load; re-zeroed by scatter

#define FMA2(d, a, b) \
    asm("fma.rn.f32x2 %0, %1, %2, %3;" : "=l"(d) : "l"(a), "l"(b), "l"(d))

__device__ __forceinline__ unsigned long long dup_f32x2(float v)
{
    unsigned long long r;
    asm("mov.b64 %0, {%1, %1};" : "=l"(r) : "r"(__float_as_uint(v)));
    return r;
}

union F2U64 {
    unsigned long long u;
    float2 f;
};

__device__ __forceinline__ uint32_t smem_u32(const void* p)
{
    uint32_t a;
    asm("{ .reg .u64 t; cvta.to.shared.u64 t, %1; cvt.u32.u64 %0, t; }"
        : "=r"(a) : "l"(p));
    return a;
}

// ------------------------- K1: HMMA input GEMM + att proj ------------------
#define K1_STRIDE 272
#define K1_SMA 0
#define K1_SMB (128 * K1_STRIDE)
#define K1_SMEM_TOTAL (128 * K1_STRIDE + 64 * K1_STRIDE)

__global__ __launch_bounds__(256) void gemm_h_hmma(
    const float* __restrict__ x, const float* __restrict__ Wlin,
    const float* __restrict__ att, int N)
{
    extern __shared__ char smem[];
    const uint32_t smem_base = smem_u32(smem);
    const int tid  = threadIdx.x;
    const int wid  = tid >> 5;
    const int lane = tid & 31;
    const int row0 = blockIdx.x * 128;

    // ---- load x tile, warp-linear: one warp = one contiguous 512B row ----
    {
        const float* xbase = x + (size_t)row0 * 128;
#pragma unroll
        for (int it = 0; it < 16; it++) {
            const int task = it * 256 + tid;       // 128 rows x 32 float4
            const int row = task >> 5;
            const int c4  = task & 31;
            float4 v = make_float4(0.f, 0.f, 0.f, 0.f);
            if (row0 + row < N)
                v = *(const float4*)&xbase[(size_t)row * 128 + c4 * 4];
            __half2 p[2];
            p[0] = __floats2half2_rn(v.x, v.y);
            p[1] = __floats2half2_rn(v.z, v.w);
            *(uint2*)(smem + K1_SMA + row * K1_STRIDE + c4 * 8) = *(uint2*)p;
        }
    }

    // ---- load Wlin, warp-linear ----
    {
#pragma unroll
        for (int it = 0; it < 8; it++) {
            const int task = it * 256 + tid;       // 64 rows x 32 float4
            const int row = task >> 5;
            const int c4  = task & 31;
            const float4 v = *(const float4*)&Wlin[(size_t)row * 128 + c4 * 4];
            __half2 p[2];
            p[0] = __floats2half2_rn(v.x, v.y);
            p[1] = __floats2half2_rn(v.z, v.w);
            *(uint2*)(smem + K1_SMB + row * K1_STRIDE + c4 * 8) = *(uint2*)p;
        }
    }
    __syncthreads();

    float acc[8][4];
#pragma unroll
    for (int nt = 0; nt < 8; nt++)
#pragma unroll
        for (int i = 0; i < 4; i++) acc[nt][i] = 0.f;

    const uint32_t aAddrBase = smem_base + K1_SMA +
        (wid * 16 + (lane & 15)) * K1_STRIDE + (lane >> 4) * 16;
    const int grp = lane >> 3;
    const int li  = lane & 7;
    const uint32_t bAddrBase = smem_base + K1_SMB +
        ((grp >> 1) * 8 + li) * K1_STRIDE + (grp & 1) * 16;

#pragma unroll
    for (int ks = 0; ks < 8; ks++) {
        uint32_t a0, a1, a2, a3;
        asm volatile(
            "ldmatrix.sync.aligned.m8n8.x4.shared.b16 {%0,%1,%2,%3}, [%4];"
            : "=r"(a0), "=r"(a1), "=r"(a2), "=r"(a3)
            : "r"(aAddrBase + ks * 32));
#pragma unroll
        for (int nt2 = 0; nt2 < 4; nt2++) {
            uint32_t b0, b1, b2, b3;
            asm volatile(
                "ldmatrix.sync.aligned.m8n8.x4.shared.b16 {%0,%1,%2,%3}, [%4];"
                : "=r"(b0), "=r"(b1), "=r"(b2), "=r"(b3)
                : "r"(bAddrBase + nt2 * 16 * K1_STRIDE + ks * 32));
            float* c0 = acc[nt2 * 2];
            float* c1 = acc[nt2 * 2 + 1];
            asm volatile(
                "mma.sync.aligned.m16n8k16.row.col.f32.f16.f16.f32 "
                "{%0,%1,%2,%3}, {%4,%5,%6,%7}, {%8,%9}, {%0,%1,%2,%3};"
                : "+f"(c0[0]), "+f"(c0[1]), "+f"(c0[2]), "+f"(c0[3])
                : "r"(a0), "r"(a1), "r"(a2), "r"(a3), "r"(b0), "r"(b1));
            asm volatile(
                "mma.sync.aligned.m16n8k16.row.col.f32.f16.f16.f32 "
                "{%0,%1,%2,%3}, {%4,%5,%6,%7}, {%8,%9}, {%0,%1,%2,%3};"
                : "+f"(c1[0]), "+f"(c1[1]), "+f"(c1[2]), "+f"(c1[3])
                : "r"(a0), "r"(a1), "r"(a2), "r"(a3), "r"(b2), "r"(b3));
        }
    }

    float2 aS[8], aD[8];
#pragma unroll
    for (int nt = 0; nt < 8; nt++) {
        const int col = nt * 8 + (lane & 3) * 2;
        aS[nt] = *(const float2*)&att[col];
        aD[nt] = *(const float2*)&att[64 + col];
    }

#pragma unroll
    for (int r = 0; r < 2; r++) {
        const int rowg = row0 + wid * 16 + (lane >> 2) + r * 8;
        const bool ok = (rowg < N);
        float sp = 0.f, dp = 0.f;
#pragma unroll
        for (int nt = 0; nt < 8; nt++) {
            const float c0 = acc[nt][r * 2 + 0];
            const float c1 = acc[nt][r * 2 + 1];
            sp += c0 * aS[nt].x + c1 * aS[nt].y;
            dp += c0 * aD[nt].x + c1 * aD[nt].y;
            if (ok)
                g_hh[(size_t)rowg * 32 + nt * 4 + (lane & 3)] =
                    __floats2half2_rn(c0, c1);
        }
        sp += __shfl_xor_sync(0xffffffffu, sp, 1);
        sp += __shfl_xor_sync(0xffffffffu, sp, 2);
        dp += __shfl_xor_sync(0xffffffffu, dp, 1);
        dp += __shfl_xor_sync(0xffffffffu, dp, 2);
        if ((lane & 3) == 0 && ok) {
            g_s[rowg] = sp;
            g_d[rowg] = dp;
        }
    }
}

// ------------------- H: histogram + per-edge rank (one pass) ---------------
__global__ __launch_bounds__(256) void hist_rank(const int* __restrict__ ei, int E)
{
    const int t = blockIdx.x * blockDim.x + threadIdx.x;
    const int e4 = t * 4;
    if (e4 + 3 < E) {
        const int4 d = *(const int4*)&ei[E + e4];
        int4 r;
        r.x = atomicAdd(&g_cnt[d.x], 1);
        r.y = atomicAdd(&g_cnt[d.y], 1);
        r.z = atomicAdd(&g_cnt[d.z], 1);
        r.w = atomicAdd(&g_cnt[d.w], 1);
        *(int4*)&g_rank[e4] = r;
    } else {
        for (int j = 0; j < 4; j++) {
            const int e = e4 + j;
            if (e < E) g_rank[e] = atomicAdd(&g_cnt[ei[E + e]], 1);
        }
    }
}

// ------------------------- S: one-launch exclusive scan --------------------
__global__ __launch_bounds__(256) void scan_fused(int N, int E, int nb)
{
    const int b = blockIdx.x;
    const int t = threadIdx.x;
    const int idx0 = b * CHUNK + t * 4;

    int v[4];
#pragma unroll
    for (int i = 0; i < 4; i++) {
        const int idx = idx0 + i;
        v[i] = (idx < N) ? g_cnt[idx] : 0;
    }
    const int tsum = v[0] + v[1] + v[2] + v[3];

    __shared__ int sm[256];
    __shared__ int blockBase;
    sm[t] = tsum;
    __syncthreads();
    for (int off = 1; off < 256; off <<= 1) {
        const int add = (t >= off) ? sm[t - off] : 0;
        __syncthreads();
        sm[t] += add;
        __syncthreads();
    }

    if (t == 0) {
        const unsigned long long pkt =
            (1ull << 63) | (unsigned long long)(unsigned)sm[255];
        __threadfence();
        atomicExch(&g_state[b], pkt);
    }

    if (t < 32) {
        int sumPrev = 0;
        for (int base = 0; base < b; base += 32) {
            const int i = base + t;
            if (i < b) {
                unsigned long long pkt;
                do {
                    pkt = atomicAdd(&g_state[i], 0ull);
                } while (!(pkt >> 63));
                sumPrev += (int)(unsigned)(pkt & 0xffffffffull);
            }
        }
#pragma unroll
        for (int m = 16; m >= 1; m >>= 1)
            sumPrev += __shfl_xor_sync(0xffffffffu, sumPrev, m);
        if (t == 0) blockBase = sumPrev;
    }
    __syncthreads();

    int run = sm[t] - tsum + blockBase;
#pragma unroll
    for (int i = 0; i < 4; i++) {
        const int idx = idx0 + i;
        if (idx < N) {
            g_off[idx] = run;
            run += v[i];
        }
    }
    if (b == 0 && t == 0) g_off[N] = E;
}

// ----------------- SC: atomic-free scatter + state re-zero -----------------
__global__ __launch_bounds__(256) void scatter_pos(const int* __restrict__ ei,
                                                   int E, int N)
{
    const int t = blockIdx.x * blockDim.x + threadIdx.x;
    const int e4 = t * 4;
    if (e4 + 3 < E) {
        const int4 s = *(const int4*)&ei[e4];
        const int4 d = *(const int4*)&ei[E + e4];
        const int4 r = *(const int4*)&g_rank[e4];
        g_srcSorted[__ldg(&g_off[d.x]) + r.x] = s.x;
        g_srcSorted[__ldg(&g_off[d.y]) + r.y] = s.y;
        g_srcSorted[__ldg(&g_off[d.z]) + r.z] = s.z;
        g_srcSorted[__ldg(&g_off[d.w]) + r.w] = s.w;
    } else {
        for (int j = 0; j < 4; j++) {
            const int e = e4 + j;
            if (e < E)
                g_srcSorted[__ldg(&g_off[ei[E + e]]) + g_rank[e]] = ei[e];
        }
    }

    if (e4 + 3 < N) {
        *(int4*)&g_cnt[e4] = make_int4(0, 0, 0, 0);
    } else if (e4 < N) {
        for (int j = 0; j < 4; j++)
            if (e4 + j < N) g_cnt[e4 + j] = 0;
    }
    if (t < NPART) g_state[t] = 0ull;
}

// ------------------------- AG: register aggregation ------------------------
__global__ __launch_bounds__(256) void agg_kernel(int N)
{
    const int warp = (blockIdx.x * blockDim.x + threadIdx.x) >> 5;
    if (warp >= N) return;
    const int lane = threadIdx.x & 31;
    const int part = lane & 7;
    const int sub  = lane >> 3;

    const int start = g_off[warp];
    const int end   = g_off[warp + 1];
    const float dnode = g_d[warp];

    unsigned long long acc2[4] = {0ull, 0ull, 0ull, 0ull};
    float wsum = 0.f;

    const int cnt = end - start;
    const int iters = (cnt + 3) >> 2;
    for (int it = 0; it < iters; ++it) {
        const int e = start + it * 4 + sub;
        const bool valid = (e < end);
        const int src = g_srcSorted[valid ? e : 0];
        float ev = g_s[src] + dnode;
        ev = (ev > 0.f) ? ev : 0.2f * ev;
        const float w = valid ? __expf(ev) : 0.f;
        if (part == 0) wsum += w;
        const unsigned long long w2 = dup_f32x2(w);
        const uint4 hvu = *(const uint4*)(((const char*)g_hh) + ((size_t)src * 128 + part * 16));
        const __half2* hp = (const __half2*)&hvu;
#pragma unroll
        for (int j = 0; j < 4; j++) {
            F2U64 hf; hf.f = __half22float2(hp[j]);
            FMA2(acc2[j], hf.u, w2);
        }
    }

#pragma unroll
    for (int j = 0; j < 4; j++) {
        F2U64 a; a.u = acc2[j];
        a.f.x += __shfl_xor_sync(0xffffffffu, a.f.x, 8);
        a.f.y += __shfl_xor_sync(0xffffffffu, a.f.y, 8);
        a.f.x += __shfl_xor_sync(0xffffffffu, a.f.x, 16);
        a.f.y += __shfl_xor_sync(0xffffffffu, a.f.y, 16);
        acc2[j] = a.u;
    }
    wsum += __shfl_xor_sync(0xffffffffu, wsum, 8);
    wsum += __shfl_xor_sync(0xffffffffu, wsum, 16);
    const float den = __shfl_sync(0xffffffffu, wsum, 0) + 1e-9f;

    if (sub == 0) {
        const float inv = 1.f / den;
        __half2 p[4];
#pragma unroll
        for (int j = 0; j < 4; j++) {
            F2U64 a; a.u = acc2[j];
            p[j] = __floats2half2_rn(fmaxf(a.f.x * inv, 0.f),
                                     fmaxf(a.f.y * inv, 0.f));
        }
        *(uint4*)&g_aggh[warp * 32 + part * 4] = *(uint4*)p;
    }
}

// ------------------------- K4: HMMA output GEMM ----------------------------
#define KO_STRIDE 144
#define KO_SMB (128 * KO_STRIDE)

__global__ __launch_bounds__(256) void gemm_out_hmma(
    const float* __restrict__ Wout, const float* __restrict__ bout,
    float* __restrict__ out, int N)
{
    __shared__ char smem[128 * KO_STRIDE + 64 * KO_STRIDE];
    const uint32_t smem_base = smem_u32(smem);
    const int tid  = threadIdx.x;
    const int wid  = tid >> 5;
    const int lane = tid & 31;
    const int row0 = blockIdx.x * 128;

    for (int task = tid; task < 128 * 8; task += 256) {
        const int row = task >> 3;
        const int c   = task & 7;
        const int grow = row0 + row;
        uint4 v = make_uint4(0u, 0u, 0u, 0u);
        if (grow < N) v = *(const uint4*)&g_aggh[(size_t)grow * 32 + c * 4];
        *(uint4*)(smem + row * KO_STRIDE + c * 16) = v;
    }

    {
        const int row = tid >> 2;
        const int q   = tid & 3;
        const float4* srcp = (const float4*)&Wout[(size_t)row * 64 + q * 16];
        char* dst = smem + KO_SMB + row * KO_STRIDE + q * 32;
#pragma unroll
        for (int j = 0; j < 2; j++) {
            const float4 v0 = srcp[2 * j];
            const float4 v1 = srcp[2 * j + 1];
            __half2 p[4];
            p[0] = __floats2half2_rn(v0.x, v0.y);
            p[1] = __floats2half2_rn(v0.z, v0.w);
            p[2] = __floats2half2_rn(v1.x, v1.y);
            p[3] = __floats2half2_rn(v1.z, v1.w);
            *(uint4*)(dst + j * 16) = *(uint4*)p;
        }
    }
    __syncthreads();

    float acc[8][4];
#pragma unroll
    for (int nt = 0; nt < 8; nt++)
#pragma unroll
        for (int i = 0; i < 4; i++) acc[nt][i] = 0.f;

    const uint32_t aAddrBase = smem_base +
        (wid * 16 + (lane & 15)) * KO_STRIDE + (lane >> 4) * 16;
    const int grp = lane >> 3;
    const int li  = lane & 7;
    const uint32_t bAddrBase = smem_base + KO_SMB +
        ((grp >> 1) * 8 + li) * KO_STRIDE + (grp & 1) * 16;

#pragma unroll
    for (int ks = 0; ks < 4; ks++) {
        uint32_t a0, a1, a2, a3;
        asm volatile(
            "ldmatrix.sync.aligned.m8n8.x4.shared.b16 {%0,%1,%2,%3}, [%4];"
            : "=r"(a0), "=r"(a1), "=r"(a2), "=r"(a3)
            : "r"(aAddrBase + ks * 32));
#pragma unroll
        for (int nt2 = 0; nt2 < 4; nt2++) {
            uint32_t b0, b1, b2, b3;
            asm volatile(
                "ldmatrix.sync.aligned.m8n8.x4.shared.b16 {%0,%1,%2,%3}, [%4];"
                : "=r"(b0), "=r"(b1), "=r"(b2), "=r"(b3)
                : "r"(bAddrBase + nt2 * 16 * KO_STRIDE + ks * 32));
            float* c0 = acc[nt2 * 2];
            float* c1 = acc[nt2 * 2 + 1];
            asm volatile(
                "mma.sync.aligned.m16n8k16.row.col.f32.f16.f16.f32 "
                "{%0,%1,%2,%3}, {%4,%5,%6,%7}, {%8,%9}, {%0,%1,%2,%3};"
                : "+f"(c0[0]), "+f"(c0[1]), "+f"(c0[2]), "+f"(c0[3])
                : "r"(a0), "r"(a1), "r"(a2), "r"(a3), "r"(b0), "r"(b1));
            asm volatile(
                "mma.sync.aligned.m16n8k16.row.col.f32.f16.f16.f32 "
                "{%0,%1,%2,%3}, {%4,%5,%6,%7}, {%8,%9}, {%0,%1,%2,%3};"
                : "+f"(c1[0]), "+f"(c1[1]), "+f"(c1[2]), "+f"(c1[3])
                : "r"(a0), "r"(a1), "r"(a2), "r"(a3), "r"(b2), "r"(b3));
        }
    }

    float2 bias[8];
#pragma unroll
    for (int nt = 0; nt < 8; nt++)
        bias[nt] = *(const float2*)&bout[nt * 8 + (lane & 3) * 2];

#pragma unroll
    for (int r = 0; r < 2; r++) {
        const int rowg = row0 + wid * 16 + (lane >> 2) + r * 8;
        if (rowg >= N) continue;
#pragma unroll
        for (int nt = 0; nt < 8; nt++) {
            const int col = nt * 8 + (lane & 3) * 2;
            float2 o;
            o.x = acc[nt][r * 2 + 0] + bias[nt].x;
            o.y = acc[nt][r * 2 + 1] + bias[nt].y;
            *(float2*)&out[(size_t)rowg * 64 + col] = o;
        }
    }
}

// ---------------------------------------------------------------------------
extern "C" void kernel_launch(void* const* d_in, const int* in_sizes, int n_in,
                              void* d_out, int out_size)
{
    const float* x    = (const float*)d_in[0];
    const int*   ei   = (const int*)d_in[1];
    const float* Wlin = (const float*)d_in[2];
    const float* att  = (const float*)d_in[3];
    const float* Wout = (const float*)d_in[4];
    const float* bout = (const float*)d_in[5];
    float* out = (float*)d_out;

    const int N = in_sizes[0] / 128;
    const int E = in_sizes[1] / 2;
    const int nb = (N + CHUNK - 1) / CHUNK;

    static cudaStream_t sB = nullptr;
    static cudaEvent_t evFork = nullptr, evJoin = nullptr;
    static bool attrSet = false;
    if (sB == nullptr) {
        cudaStreamCreateWithFlags(&sB, cudaStreamNonBlocking);
        cudaEventCreateWithFlags(&evFork, cudaEventDisableTiming);
        cudaEventCreateWithFlags(&evJoin, cudaEventDisableTiming);
    }
    if (!attrSet) {
        cudaFuncSetAttribute(gemm_h_hmma,
                             cudaFuncAttributeMaxDynamicSharedMemorySize,
                             K1_SMEM_TOTAL);
        attrSet = true;
    }

    if (sB != nullptr) {
        cudaEventRecord(evFork, 0);
        cudaStreamWaitEvent(sB, evFork, 0);

        hist_rank<<<(E / 4 + 255) / 256 + 1, 256, 0, sB>>>(ei, E);
        scan_fused<<<nb, 256, 0, sB>>>(N, E, nb);
        scatter_pos<<<(E / 4 + 255) / 256 + 1, 256, 0, sB>>>(ei, E, N);
        cudaEventRecord(evJoin, sB);

        gemm_h_hmma<<<(N + 127) / 128, 256, K1_SMEM_TOTAL>>>(x, Wlin, att, N);

        cudaStreamWaitEvent(0, evJoin, 0);
    } else {
        gemm_h_hmma<<<(N + 127) / 128, 256, K1_SMEM_TOTAL>>>(x, Wlin, att, N);
        hist_rank<<<(E / 4 + 255) / 256 + 1, 256>>>(ei, E);
        scan_fused<<<nb, 256>>>(N, E, nb);
        scatter_pos<<<(E / 4 + 255) / 256 + 1, 256>>>(ei, E, N);
    }

    agg_kernel<<<(N * 32 + 255) / 256, 256>>>(N);
    gemm_out_hmma<<<(N + 127) / 128, 256>>>(Wout, bout, out, N);
}